// round 1
// baseline (speedup 1.0000x reference)
#include <cuda_runtime.h>
#include <math.h>

#define BB 32
#define HH 1024
#define EE 512
#define VV 32001
#define NSTEP 32
#define PC 32256          // padded projection cols = 126*256
#define PB 126            // projection blocks
#define KSPL 8            // k-split for gate GEMMs

// ---------------- device state (static allocations only) ----------------
__device__ float d_w0T[1536 * 4096];     // [xT(512); h0T(1024)] k-major, 4096 gate cols
__device__ float d_w1T[2048 * 4096];     // [h0T(1024); h1T(1024)] k-major
__device__ float d_woT[1024 * PC];       // w_out k-major, padded cols (pad stays 0)
__device__ float d_act[2560 * BB];       // rows: 0..511 xT, 512..1535 h0T, 1536..2559 h1T
__device__ float d_cst[2 * HH * BB];     // cell state [layer][j][b]
__device__ float d_gp[KSPL * 4096 * BB]; // gate GEMM partials [ks][col][b]
__device__ float d_pmax[PB * BB];
__device__ int   d_pidx[PB * BB];
__device__ int   d_tok[BB];
__device__ int   d_run[BB];
__device__ int   d_len[BB];

typedef unsigned long long ull;

__device__ __forceinline__ ull pack2(float lo, float hi) {
    ull r; asm("mov.b64 %0,{%1,%2};" : "=l"(r) : "f"(lo), "f"(hi)); return r;
}
__device__ __forceinline__ ull fma2(ull a, ull b, ull c) {
    ull d; asm("fma.rn.f32x2 %0,%1,%2,%3;" : "=l"(d) : "l"(a), "l"(b), "l"(c)); return d;
}
__device__ __forceinline__ float2 unpk(ull a) {
    float2 f; asm("mov.b64 {%0,%1},%2;" : "=f"(f.x), "=f"(f.y) : "l"(a)); return f;
}

// ---------------- init ----------------
__global__ void k_init(const float* __restrict__ h0, const float* __restrict__ c0) {
    int t = blockIdx.x * blockDim.x + threadIdx.x;
    if (t < 2 * BB * HH) {
        int l = t / (BB * HH);
        int r = t % (BB * HH);
        int b = r / HH;
        int j = r % HH;
        d_act[(512 + l * HH + j) * BB + b] = h0[t];
        d_cst[(l * HH + j) * BB + b] = c0[t];
    }
    if (t < BB) { d_tok[t] = 32000; d_run[t] = 1; d_len[t] = 0; }
}

// ---------------- weight transpose: in[R][K] -> out[k][origRow], tiled ----------------
__device__ __forceinline__ float* t_out(int id) {
    switch (id) {
        case 0: return d_w0T;
        case 1: return d_w0T + 512 * 4096;
        case 2: return d_w1T;
        case 3: return d_w1T + 1024 * 4096;
        default: return d_woT;
    }
}

__global__ void k_transpose(const float* __restrict__ in, int R, int K, int outStride, int id) {
    __shared__ float tile[32][33];
    float* out = t_out(id);
    int kb = blockIdx.x * 32, rb = blockIdx.y * 32;
    int tx = threadIdx.x, ty = threadIdx.y;
#pragma unroll
    for (int i = 0; i < 32; i += 8) {
        int r = rb + ty + i, k = kb + tx;
        tile[ty + i][tx] = (r < R) ? in[(size_t)r * K + k] : 0.f;
    }
    __syncthreads();
#pragma unroll
    for (int i = 0; i < 32; i += 8) {
        int k = kb + ty + i, r = rb + tx;
        if (r < outStride) out[(size_t)k * outStride + r] = tile[tx][ty + i];
    }
}

// ---------------- select (argmax reduce + token/len update) ----------------
__global__ void k_select(float* __restrict__ outp, int has_len, int s) {
    __shared__ float sv[BB][8];
    __shared__ int   si[BB][8];
    int t = threadIdx.x;
    if (s > 0) {
        int b = t >> 3, q = t & 7;
        float best = -3.402823466e38f; int bi = 0x7fffffff;
        for (int p = q; p < PB; p += 8) {
            float v = d_pmax[p * BB + b]; int id = d_pidx[p * BB + b];
            if (v > best || (v == best && id < bi)) { best = v; bi = id; }
        }
        sv[b][q] = best; si[b][q] = bi;
        __syncthreads();
        if (q == 0) {
#pragma unroll
            for (int p = 1; p < 8; p++) {
                float v = sv[b][p]; int id = si[b][p];
                if (v > best || (v == best && id < bi)) { best = v; bi = id; }
            }
            d_tok[b] = bi;
            int r2 = d_run[b] && (bi != 32000);
            d_run[b] = r2;
            if (r2) d_len[b] = s;   // (s-1)+1
            if (has_len) outp[(size_t)NSTEP * BB * VV + b] = (float)d_len[b];
        }
    }
}

// ---------------- embedding gather (transposed) ----------------
__global__ void k_embed(const float* __restrict__ emb) {
    int i = blockIdx.x * 256 + threadIdx.x;   // 16384 total
    int b = i >> 9, k = i & 511;
    d_act[k * BB + b] = emb[(size_t)d_tok[b] * EE + k];
}

// ---------------- gate GEMM (k-split partials) ----------------
__global__ void __launch_bounds__(256) k_gates(int layer) {
    __shared__ __align__(16) float xs[256 * BB];
    const float* wT = layer ? d_w1T : d_w0T;
    int rowStart = layer ? 512 : 0;
    int Ktot = layer ? 2048 : 1536;
    int slice = Ktot >> 3;
    int k0 = blockIdx.y * slice;
    int tid = threadIdx.x;

    const float4* src = (const float4*)(d_act + (rowStart + k0) * BB);
    float4* dst = (float4*)xs;
    int nf = slice * BB / 4;
    for (int i = tid; i < nf; i += 256) dst[i] = src[i];
    __syncthreads();

    int w = tid >> 5, lane = tid & 31, cl = lane & 7, bg = lane >> 3;
    int col = blockIdx.x * 256 + w * 32 + cl * 4;

    ull acc[4][4];
#pragma unroll
    for (int i = 0; i < 4; i++)
#pragma unroll
        for (int j = 0; j < 4; j++) acc[i][j] = 0ull;

    const float* wr = wT + (size_t)k0 * 4096 + col;
    const float* xb = xs + bg * 8;
#pragma unroll 4
    for (int kk = 0; kk < slice; kk++) {
        float4 w4 = *(const float4*)wr; wr += 4096;
        const float* xp = xb + kk * BB;
        ull x0 = *(const ull*)(xp);
        ull x1 = *(const ull*)(xp + 2);
        ull x2 = *(const ull*)(xp + 4);
        ull x3 = *(const ull*)(xp + 6);
        ull wv0 = pack2(w4.x, w4.x), wv1 = pack2(w4.y, w4.y);
        ull wv2 = pack2(w4.z, w4.z), wv3 = pack2(w4.w, w4.w);
        acc[0][0] = fma2(wv0, x0, acc[0][0]); acc[0][1] = fma2(wv0, x1, acc[0][1]);
        acc[0][2] = fma2(wv0, x2, acc[0][2]); acc[0][3] = fma2(wv0, x3, acc[0][3]);
        acc[1][0] = fma2(wv1, x0, acc[1][0]); acc[1][1] = fma2(wv1, x1, acc[1][1]);
        acc[1][2] = fma2(wv1, x2, acc[1][2]); acc[1][3] = fma2(wv1, x3, acc[1][3]);
        acc[2][0] = fma2(wv2, x0, acc[2][0]); acc[2][1] = fma2(wv2, x1, acc[2][1]);
        acc[2][2] = fma2(wv2, x2, acc[2][2]); acc[2][3] = fma2(wv2, x3, acc[2][3]);
        acc[3][0] = fma2(wv3, x0, acc[3][0]); acc[3][1] = fma2(wv3, x1, acc[3][1]);
        acc[3][2] = fma2(wv3, x2, acc[3][2]); acc[3][3] = fma2(wv3, x3, acc[3][3]);
    }
#pragma unroll
    for (int i = 0; i < 4; i++) {
        size_t base = ((size_t)blockIdx.y * 4096 + col + i) * BB + bg * 8;
        *(ull*)(d_gp + base)     = acc[i][0];
        *(ull*)(d_gp + base + 2) = acc[i][1];
        *(ull*)(d_gp + base + 4) = acc[i][2];
        *(ull*)(d_gp + base + 6) = acc[i][3];
    }
}

// ---------------- LSTM elementwise update ----------------
__global__ void k_update(const float* __restrict__ bih, const float* __restrict__ bhh, int layer) {
    int g = blockIdx.x * 256 + threadIdx.x;
    int j = g >> 5, b = g & 31;
    float gate[4];
#pragma unroll
    for (int q = 0; q < 4; q++) {
        int col = q * HH + j;
        float a = bih[col] + bhh[col];
#pragma unroll
        for (int ks = 0; ks < KSPL; ks++) a += d_gp[((size_t)ks * 4096 + col) * BB + b];
        gate[q] = a;
    }
    int ci = (layer * HH + j) * BB + b;
    float c = d_cst[ci];
    float ig = 1.f / (1.f + expf(-gate[0]));
    float fg = 1.f / (1.f + expf(-gate[1]));
    float gg = tanhf(gate[2]);
    float og = 1.f / (1.f + expf(-gate[3]));
    float c2 = fg * c + ig * gg;
    float h2 = og * tanhf(c2);
    d_cst[ci] = c2;
    d_act[(512 + layer * HH + j) * BB + b] = h2;
}

// ---------------- output projection + logit store + partial argmax ----------------
__global__ void __launch_bounds__(256) k_proj(const float* __restrict__ bias,
                                              float* __restrict__ outp, int s) {
    __shared__ __align__(16) float xs[128 * BB];
    __shared__ float rv[BB][64];
    __shared__ int   ri[BB][64];

    int tid = threadIdx.x, w = tid >> 5, lane = tid & 31, cl = lane & 7, bg = lane >> 3;
    int col = blockIdx.x * 256 + w * 32 + cl * 4;

    ull acc[4][4];
#pragma unroll
    for (int i = 0; i < 4; i++)
#pragma unroll
        for (int j = 0; j < 4; j++) acc[i][j] = 0ull;

    for (int k0 = 0; k0 < HH; k0 += 128) {
        const float4* src = (const float4*)(d_act + (1536 + k0) * BB);
        float4* dst = (float4*)xs;
        for (int i = tid; i < 128 * BB / 4; i += 256) dst[i] = src[i];
        __syncthreads();
        const float* wr = d_woT + (size_t)k0 * PC + col;
        const float* xb = xs + bg * 8;
#pragma unroll 4
        for (int kk = 0; kk < 128; kk++) {
            float4 w4 = *(const float4*)wr; wr += PC;
            const float* xp = xb + kk * BB;
            ull x0 = *(const ull*)(xp);
            ull x1 = *(const ull*)(xp + 2);
            ull x2 = *(const ull*)(xp + 4);
            ull x3 = *(const ull*)(xp + 6);
            ull wv0 = pack2(w4.x, w4.x), wv1 = pack2(w4.y, w4.y);
            ull wv2 = pack2(w4.z, w4.z), wv3 = pack2(w4.w, w4.w);
            acc[0][0] = fma2(wv0, x0, acc[0][0]); acc[0][1] = fma2(wv0, x1, acc[0][1]);
            acc[0][2] = fma2(wv0, x2, acc[0][2]); acc[0][3] = fma2(wv0, x3, acc[0][3]);
            acc[1][0] = fma2(wv1, x0, acc[1][0]); acc[1][1] = fma2(wv1, x1, acc[1][1]);
            acc[1][2] = fma2(wv1, x2, acc[1][2]); acc[1][3] = fma2(wv1, x3, acc[1][3]);
            acc[2][0] = fma2(wv2, x0, acc[2][0]); acc[2][1] = fma2(wv2, x1, acc[2][1]);
            acc[2][2] = fma2(wv2, x2, acc[2][2]); acc[2][3] = fma2(wv2, x3, acc[2][3]);
            acc[3][0] = fma2(wv3, x0, acc[3][0]); acc[3][1] = fma2(wv3, x1, acc[3][1]);
            acc[3][2] = fma2(wv3, x2, acc[3][2]); acc[3][3] = fma2(wv3, x3, acc[3][3]);
        }
        __syncthreads();
    }

    // epilogue: bias, store logits, local argmax (8 batches per lane)
    float bv[8]; int bx[8];
#pragma unroll
    for (int j = 0; j < 8; j++) { bv[j] = -3.402823466e38f; bx[j] = VV; }
#pragma unroll
    for (int i = 0; i < 4; i++) {
        int c = col + i;
        if (c < VV) {
            float bb = bias[c];
#pragma unroll
            for (int j = 0; j < 4; j++) {
                float2 u = unpk(acc[i][j]);
                u.x += bb; u.y += bb;
                size_t o0 = (size_t)s * BB * VV + (size_t)(bg * 8 + 2 * j) * VV + c;
                outp[o0] = u.x;
                outp[o0 + VV] = u.y;
                if (u.x > bv[2 * j]     || (u.x == bv[2 * j]     && c < bx[2 * j]))     { bv[2 * j] = u.x;     bx[2 * j] = c; }
                if (u.y > bv[2 * j + 1] || (u.y == bv[2 * j + 1] && c < bx[2 * j + 1])) { bv[2 * j + 1] = u.y; bx[2 * j + 1] = c; }
            }
        }
    }
    int slot = w * 8 + cl;
#pragma unroll
    for (int j = 0; j < 8; j++) { rv[bg * 8 + j][slot] = bv[j]; ri[bg * 8 + j][slot] = bx[j]; }
    __syncthreads();
    if (tid < BB) {
        float best = -3.402823466e38f; int bi = VV;
        for (int p = 0; p < 64; p++) {
            float v = rv[tid][p]; int id = ri[tid][p];
            if (v > best || (v == best && id < bi)) { best = v; bi = id; }
        }
        d_pmax[blockIdx.x * BB + tid] = best;
        d_pidx[blockIdx.x * BB + tid] = bi;
    }
}

// ---------------- launch ----------------
extern "C" void kernel_launch(void* const* d_in, const int* in_sizes, int n_in,
                              void* d_out, int out_size) {
    const float* h0   = (const float*)d_in[2];
    const float* c0   = (const float*)d_in[3];
    const float* emb  = (const float*)d_in[4];
    const float* wih0 = (const float*)d_in[5];
    const float* whh0 = (const float*)d_in[6];
    const float* bih0 = (const float*)d_in[7];
    const float* bhh0 = (const float*)d_in[8];
    const float* wih1 = (const float*)d_in[9];
    const float* whh1 = (const float*)d_in[10];
    const float* bih1 = (const float*)d_in[11];
    const float* bhh1 = (const float*)d_in[12];
    const float* wout = (const float*)d_in[13];
    const float* bout = (const float*)d_in[14];
    float* outp = (float*)d_out;
    int has_len = out_size > NSTEP * BB * VV;

    dim3 tb(32, 8);
    k_transpose<<<dim3(512 / 32, 4096 / 32), tb>>>(wih0, 4096, 512, 4096, 0);
    k_transpose<<<dim3(1024 / 32, 4096 / 32), tb>>>(whh0, 4096, 1024, 4096, 1);
    k_transpose<<<dim3(1024 / 32, 4096 / 32), tb>>>(wih1, 4096, 1024, 4096, 2);
    k_transpose<<<dim3(1024 / 32, 4096 / 32), tb>>>(whh1, 4096, 1024, 4096, 3);
    k_transpose<<<dim3(1024 / 32, (VV + 31) / 32), tb>>>(wout, VV, 1024, PC, 4);
    k_init<<<(2 * BB * HH + 255) / 256, 256>>>(h0, c0);

    for (int s = 0; s < NSTEP; s++) {
        k_select<<<1, 256>>>(outp, has_len, s);
        k_embed<<<BB * EE / 256, 256>>>(emb);
        k_gates<<<dim3(16, KSPL), 256>>>(0);
        k_update<<<HH * BB / 256, 256>>>(bih0, bhh0, 0);
        k_gates<<<dim3(16, KSPL), 256>>>(1);
        k_update<<<HH * BB / 256, 256>>>(bih1, bhh1, 1);
        k_proj<<<PB, 256>>>(bout, outp, s);
    }
    k_select<<<1, 256>>>(outp, has_len, NSTEP);
}

// round 2
// speedup vs baseline: 1.4650x; 1.4650x over previous
#include <cuda_runtime.h>
#include <math.h>

#define BB 32
#define HH 1024
#define EE 512
#define VV 32001
#define NSTEP 32
#define PC 32256          // padded projection cols = 126*256
#define PB 126            // projection blocks
#define KSPL 8            // k-split for gate GEMMs

// ---------------- device state (static allocations only) ----------------
__device__ float d_w0T[1536 * 4096];     // [xT(512); h0T(1024)] k-major, 4096 gate cols
__device__ float d_w1T[2048 * 4096];     // [h0T(1024); h1T(1024)] k-major
__device__ float d_woT[1024 * PC];       // w_out k-major, padded cols (pad stays 0)
__device__ float d_act[2560 * BB];       // rows: 0..511 xT, 512..1535 h0T, 1536..2559 h1T
__device__ float d_cst[2 * HH * BB];     // cell state [layer][j][b]
__device__ float d_gp[KSPL * 4096 * BB]; // gate GEMM partials [ks][col][b]
__device__ float d_pmax[PB * BB];
__device__ int   d_pidx[PB * BB];
__device__ int   d_tok[BB];
__device__ int   d_run[BB];
__device__ int   d_len[BB];

typedef unsigned long long ull;

__device__ __forceinline__ ull pack2(float lo, float hi) {
    ull r; asm("mov.b64 %0,{%1,%2};" : "=l"(r) : "f"(lo), "f"(hi)); return r;
}
__device__ __forceinline__ ull fma2(ull a, ull b, ull c) {
    ull d; asm("fma.rn.f32x2 %0,%1,%2,%3;" : "=l"(d) : "l"(a), "l"(b), "l"(c)); return d;
}
__device__ __forceinline__ float2 unpk(ull a) {
    float2 f; asm("mov.b64 {%0,%1},%2;" : "=f"(f.x), "=f"(f.y) : "l"(a)); return f;
}

// ---------------- init ----------------
__global__ void k_init(const float* __restrict__ h0, const float* __restrict__ c0) {
    int t = blockIdx.x * blockDim.x + threadIdx.x;
    if (t < 2 * BB * HH) {
        int l = t / (BB * HH);
        int r = t % (BB * HH);
        int b = r / HH;
        int j = r % HH;
        d_act[(512 + l * HH + j) * BB + b] = h0[t];
        d_cst[(l * HH + j) * BB + b] = c0[t];
    }
    if (t < BB) { d_tok[t] = 32000; d_run[t] = 1; d_len[t] = 0; }
}

// ---------------- weight transpose: in[R][K] -> out[k][origRow], tiled ----------------
__device__ __forceinline__ float* t_out(int id) {
    switch (id) {
        case 0: return d_w0T;
        case 1: return d_w0T + 512 * 4096;
        case 2: return d_w1T;
        case 3: return d_w1T + 1024 * 4096;
        default: return d_woT;
    }
}

__global__ void k_transpose(const float* __restrict__ in, int R, int K, int outStride, int id) {
    __shared__ float tile[32][33];
    float* out = t_out(id);
    int kb = blockIdx.x * 32, rb = blockIdx.y * 32;
    int tx = threadIdx.x, ty = threadIdx.y;
#pragma unroll
    for (int i = 0; i < 32; i += 8) {
        int r = rb + ty + i, k = kb + tx;
        tile[ty + i][tx] = (r < R) ? in[(size_t)r * K + k] : 0.f;
    }
    __syncthreads();
#pragma unroll
    for (int i = 0; i < 32; i += 8) {
        int k = kb + ty + i, r = rb + tx;
        if (r < outStride) out[(size_t)k * outStride + r] = tile[tx][ty + i];
    }
}

// ---------------- fused select (argmax) + embedding gather ----------------
// grid = 32 (one block per batch), block = 512
__global__ void __launch_bounds__(512) k_selembed(const float* __restrict__ emb,
                                                  float* __restrict__ outp,
                                                  int has_len, int s) {
    __shared__ float sv[128];
    __shared__ int   si[128];
    int b = blockIdx.x;
    int t = threadIdx.x;

    if (s > 0) {
        if (t < 128) {
            float best = -3.402823466e38f; int bi = 0x7fffffff;
            if (t < PB) { best = d_pmax[t * BB + b]; bi = d_pidx[t * BB + b]; }
            sv[t] = best; si[t] = bi;
        }
        __syncthreads();
        if (t == 0) {
            float best = sv[0]; int bi = si[0];
            for (int p = 1; p < 128; p++) {
                float v = sv[p]; int id = si[p];
                if (v > best || (v == best && id < bi)) { best = v; bi = id; }
            }
            d_tok[b] = bi;
            int r2 = d_run[b] && (bi != 32000);
            d_run[b] = r2;
            if (r2) d_len[b] = s;
            if (has_len) outp[(size_t)NSTEP * BB * VV + b] = (float)d_len[b];
        }
        __syncthreads();
    }
    int tok = d_tok[b];
    d_act[t * BB + b] = emb[(size_t)tok * EE + t];   // t = 0..511 == EE
}

// ---------------- gate GEMM (k-split partials, 8-deep load batching) ----------------
__global__ void __launch_bounds__(256) k_gates(int layer) {
    __shared__ __align__(16) float xs[256 * BB];
    const float* wT = layer ? d_w1T : d_w0T;
    int rowStart = layer ? 512 : 0;
    int Ktot = layer ? 2048 : 1536;
    int slice = Ktot >> 3;
    int k0 = blockIdx.y * slice;
    int tid = threadIdx.x;

    const float4* src = (const float4*)(d_act + (rowStart + k0) * BB);
    float4* dst = (float4*)xs;
    int nf = slice * BB / 4;
    for (int i = tid; i < nf; i += 256) dst[i] = src[i];
    __syncthreads();

    int w = tid >> 5, lane = tid & 31, cl = lane & 7, bg = lane >> 3;
    int col = blockIdx.x * 256 + w * 32 + cl * 4;

    ull acc[4][4];
#pragma unroll
    for (int i = 0; i < 4; i++)
#pragma unroll
        for (int j = 0; j < 4; j++) acc[i][j] = 0ull;

    const float* wr = wT + (size_t)k0 * 4096 + col;
    const float* xb = xs + bg * 8;
    for (int kk0 = 0; kk0 < slice; kk0 += 8) {
        float4 wv[8];
#pragma unroll
        for (int j = 0; j < 8; j++) wv[j] = *(const float4*)(wr + (size_t)j * 4096);
        wr += (size_t)8 * 4096;
#pragma unroll
        for (int j = 0; j < 8; j++) {
            const float* xp = xb + (kk0 + j) * BB;
            ull x0 = *(const ull*)(xp);
            ull x1 = *(const ull*)(xp + 2);
            ull x2 = *(const ull*)(xp + 4);
            ull x3 = *(const ull*)(xp + 6);
            ull wv0 = pack2(wv[j].x, wv[j].x), wv1 = pack2(wv[j].y, wv[j].y);
            ull wv2 = pack2(wv[j].z, wv[j].z), wv3 = pack2(wv[j].w, wv[j].w);
            acc[0][0] = fma2(wv0, x0, acc[0][0]); acc[0][1] = fma2(wv0, x1, acc[0][1]);
            acc[0][2] = fma2(wv0, x2, acc[0][2]); acc[0][3] = fma2(wv0, x3, acc[0][3]);
            acc[1][0] = fma2(wv1, x0, acc[1][0]); acc[1][1] = fma2(wv1, x1, acc[1][1]);
            acc[1][2] = fma2(wv1, x2, acc[1][2]); acc[1][3] = fma2(wv1, x3, acc[1][3]);
            acc[2][0] = fma2(wv2, x0, acc[2][0]); acc[2][1] = fma2(wv2, x1, acc[2][1]);
            acc[2][2] = fma2(wv2, x2, acc[2][2]); acc[2][3] = fma2(wv2, x3, acc[2][3]);
            acc[3][0] = fma2(wv3, x0, acc[3][0]); acc[3][1] = fma2(wv3, x1, acc[3][1]);
            acc[3][2] = fma2(wv3, x2, acc[3][2]); acc[3][3] = fma2(wv3, x3, acc[3][3]);
        }
    }
#pragma unroll
    for (int i = 0; i < 4; i++) {
        size_t base = ((size_t)blockIdx.y * 4096 + col + i) * BB + bg * 8;
        *(ull*)(d_gp + base)     = acc[i][0];
        *(ull*)(d_gp + base + 2) = acc[i][1];
        *(ull*)(d_gp + base + 4) = acc[i][2];
        *(ull*)(d_gp + base + 6) = acc[i][3];
    }
}

// ---------------- LSTM elementwise update ----------------
__global__ void k_update(const float* __restrict__ bih, const float* __restrict__ bhh, int layer) {
    int g = blockIdx.x * 256 + threadIdx.x;
    int j = g >> 5, b = g & 31;
    float gate[4];
#pragma unroll
    for (int q = 0; q < 4; q++) {
        int col = q * HH + j;
        float a = bih[col] + bhh[col];
#pragma unroll
        for (int ks = 0; ks < KSPL; ks++) a += d_gp[((size_t)ks * 4096 + col) * BB + b];
        gate[q] = a;
    }
    int ci = (layer * HH + j) * BB + b;
    float c = d_cst[ci];
    float ig = 1.f / (1.f + expf(-gate[0]));
    float fg = 1.f / (1.f + expf(-gate[1]));
    float gg = tanhf(gate[2]);
    float og = 1.f / (1.f + expf(-gate[3]));
    float c2 = fg * c + ig * gg;
    float h2 = og * tanhf(c2);
    d_cst[ci] = c2;
    d_act[(512 + layer * HH + j) * BB + b] = h2;
}

// ---------------- output projection: 512 thr, internal k-split, batched loads ----------------
__global__ void __launch_bounds__(512) k_proj(const float* __restrict__ bias,
                                              float* __restrict__ outp, int s) {
    __shared__ __align__(16) float xs[8192];   // 2 halves x 128k x 32b; reused as partial buf
    __shared__ float rv[BB][64];
    __shared__ int   ri[BB][64];

    int tid = threadIdx.x;
    int half = tid >> 8;          // 0/1: k range [0,512) / [512,1024)
    int t = tid & 255;
    int w = t >> 5, lane = t & 31, cl = lane & 7, bg = lane >> 3;
    int col = blockIdx.x * 256 + w * 32 + cl * 4;

    ull acc[4][4];
#pragma unroll
    for (int i = 0; i < 4; i++)
#pragma unroll
        for (int j = 0; j < 4; j++) acc[i][j] = 0ull;

    for (int cc = 0; cc < 4; cc++) {
        int kb = half * 512 + cc * 128;
        const float4* src = (const float4*)(d_act + (1536 + kb) * BB);
        float4* dst = (float4*)(xs + half * 4096);
        for (int i = t; i < 128 * BB / 4; i += 256) dst[i] = src[i];
        __syncthreads();

        const float* wr = d_woT + (size_t)kb * PC + col;
        const float* xb = xs + half * 4096 + bg * 8;
        for (int kk0 = 0; kk0 < 128; kk0 += 8) {
            float4 wv[8];
#pragma unroll
            for (int j = 0; j < 8; j++) wv[j] = *(const float4*)(wr + (size_t)j * PC);
            wr += (size_t)8 * PC;
#pragma unroll
            for (int j = 0; j < 8; j++) {
                const float* xp = xb + (kk0 + j) * BB;
                ull x0 = *(const ull*)(xp);
                ull x1 = *(const ull*)(xp + 2);
                ull x2 = *(const ull*)(xp + 4);
                ull x3 = *(const ull*)(xp + 6);
                ull wv0 = pack2(wv[j].x, wv[j].x), wv1 = pack2(wv[j].y, wv[j].y);
                ull wv2 = pack2(wv[j].z, wv[j].z), wv3 = pack2(wv[j].w, wv[j].w);
                acc[0][0] = fma2(wv0, x0, acc[0][0]); acc[0][1] = fma2(wv0, x1, acc[0][1]);
                acc[0][2] = fma2(wv0, x2, acc[0][2]); acc[0][3] = fma2(wv0, x3, acc[0][3]);
                acc[1][0] = fma2(wv1, x0, acc[1][0]); acc[1][1] = fma2(wv1, x1, acc[1][1]);
                acc[1][2] = fma2(wv1, x2, acc[1][2]); acc[1][3] = fma2(wv1, x3, acc[1][3]);
                acc[2][0] = fma2(wv2, x0, acc[2][0]); acc[2][1] = fma2(wv2, x1, acc[2][1]);
                acc[2][2] = fma2(wv2, x2, acc[2][2]); acc[2][3] = fma2(wv2, x3, acc[2][3]);
                acc[3][0] = fma2(wv3, x0, acc[3][0]); acc[3][1] = fma2(wv3, x1, acc[3][1]);
                acc[3][2] = fma2(wv3, x2, acc[3][2]); acc[3][3] = fma2(wv3, x3, acc[3][3]);
            }
        }
        __syncthreads();
    }

    // unpack accumulators to flat registers
    float f[32];
#pragma unroll
    for (int i = 0; i < 4; i++)
#pragma unroll
        for (int j = 0; j < 4; j++) {
            float2 u = unpk(acc[i][j]);
            f[i * 8 + 2 * j] = u.x;
            f[i * 8 + 2 * j + 1] = u.y;
        }

    // combine halves through smem (rotated, bank-conflict-free)
    if (half == 1) {
        float* ps = xs + (size_t)t * 32;
#pragma unroll
        for (int i = 0; i < 32; i++) ps[(i + t) & 31] = f[i];
    }
    __syncthreads();

    if (half == 0) {
        const float* ps = xs + (size_t)t * 32;
#pragma unroll
        for (int i = 0; i < 32; i++) f[i] += ps[(i + t) & 31];

        float bv[8]; int bx[8];
#pragma unroll
        for (int j = 0; j < 8; j++) { bv[j] = -3.402823466e38f; bx[j] = VV; }
#pragma unroll
        for (int i = 0; i < 4; i++) {
            int c = col + i;
            if (c < VV) {
                float bb = bias[c];
#pragma unroll
                for (int j = 0; j < 4; j++) {
                    float ux = f[i * 8 + 2 * j] + bb;
                    float uy = f[i * 8 + 2 * j + 1] + bb;
                    size_t o0 = (size_t)s * BB * VV + (size_t)(bg * 8 + 2 * j) * VV + c;
                    outp[o0] = ux;
                    outp[o0 + VV] = uy;
                    if (ux > bv[2 * j]     || (ux == bv[2 * j]     && c < bx[2 * j]))     { bv[2 * j] = ux;     bx[2 * j] = c; }
                    if (uy > bv[2 * j + 1] || (uy == bv[2 * j + 1] && c < bx[2 * j + 1])) { bv[2 * j + 1] = uy; bx[2 * j + 1] = c; }
                }
            }
        }
        int slot = w * 8 + cl;
#pragma unroll
        for (int j = 0; j < 8; j++) { rv[bg * 8 + j][slot] = bv[j]; ri[bg * 8 + j][slot] = bx[j]; }
    }
    __syncthreads();

    if (tid < BB) {
        float best = -3.402823466e38f; int bi = VV;
        for (int p = 0; p < 64; p++) {
            float v = rv[tid][p]; int id = ri[tid][p];
            if (v > best || (v == best && id < bi)) { best = v; bi = id; }
        }
        d_pmax[blockIdx.x * BB + tid] = best;
        d_pidx[blockIdx.x * BB + tid] = bi;
    }
}

// ---------------- launch ----------------
extern "C" void kernel_launch(void* const* d_in, const int* in_sizes, int n_in,
                              void* d_out, int out_size) {
    const float* h0   = (const float*)d_in[2];
    const float* c0   = (const float*)d_in[3];
    const float* emb  = (const float*)d_in[4];
    const float* wih0 = (const float*)d_in[5];
    const float* whh0 = (const float*)d_in[6];
    const float* bih0 = (const float*)d_in[7];
    const float* bhh0 = (const float*)d_in[8];
    const float* wih1 = (const float*)d_in[9];
    const float* whh1 = (const float*)d_in[10];
    const float* bih1 = (const float*)d_in[11];
    const float* bhh1 = (const float*)d_in[12];
    const float* wout = (const float*)d_in[13];
    const float* bout = (const float*)d_in[14];
    float* outp = (float*)d_out;
    int has_len = out_size > NSTEP * BB * VV;

    dim3 tb(32, 8);
    k_transpose<<<dim3(512 / 32, 4096 / 32), tb>>>(wih0, 4096, 512, 4096, 0);
    k_transpose<<<dim3(1024 / 32, 4096 / 32), tb>>>(whh0, 4096, 1024, 4096, 1);
    k_transpose<<<dim3(1024 / 32, 4096 / 32), tb>>>(wih1, 4096, 1024, 4096, 2);
    k_transpose<<<dim3(1024 / 32, 4096 / 32), tb>>>(whh1, 4096, 1024, 4096, 3);
    k_transpose<<<dim3(1024 / 32, (VV + 31) / 32), tb>>>(wout, VV, 1024, PC, 4);
    k_init<<<(2 * BB * HH + 255) / 256, 256>>>(h0, c0);

    for (int s = 0; s < NSTEP; s++) {
        k_selembed<<<BB, 512>>>(emb, outp, has_len, s);
        k_gates<<<dim3(16, KSPL), 256>>>(0);
        k_update<<<HH * BB / 256, 256>>>(bih0, bhh0, 0);
        k_gates<<<dim3(16, KSPL), 256>>>(1);
        k_update<<<HH * BB / 256, 256>>>(bih1, bhh1, 1);
        k_proj<<<PB, 512>>>(bout, outp, s);
    }
    k_selembed<<<BB, 512>>>(emb, outp, has_len, NSTEP);
}

// round 3
// speedup vs baseline: 2.9635x; 2.0229x over previous
#include <cuda_runtime.h>
#include <math.h>
#include <stdint.h>

#define BB 32
#define HH 1024
#define EE 512
#define VV 32001
#define NSTEP 32
#define PC 32256          // padded projection cols = 126*256
#define PB 126            // projection blocks

// ---------------- device state ----------------
__device__ float d_w0T[1536 * 4096];   // layer0 gate weights, k-major, cols c'=j*4+g
__device__ float d_w1T[2048 * 4096];   // layer1 gate weights
__device__ float d_woT[1024 * PC];     // w_out k-major, padded cols (pad zeros)
__device__ float d_h[2][2][HH * BB];   // [parity][layer][j*32+b]
__device__ float d_x[EE * BB];         // embedded token, [k*32+b]
__device__ float d_cst[2 * HH * BB];   // cell state [layer][j][b]
__device__ float d_pmax[PB * BB];
__device__ int   d_pidx[PB * BB];
__device__ int   d_tok[BB];
__device__ int   d_run[BB];
__device__ int   d_len[BB];

typedef unsigned long long ull;

__device__ __forceinline__ ull pack2(float lo, float hi) {
    ull r; asm("mov.b64 %0,{%1,%2};" : "=l"(r) : "f"(lo), "f"(hi)); return r;
}
__device__ __forceinline__ ull fma2(ull a, ull b, ull c) {
    ull d; asm("fma.rn.f32x2 %0,%1,%2,%3;" : "=l"(d) : "l"(a), "l"(b), "l"(c)); return d;
}
__device__ __forceinline__ float2 unpk(ull a) {
    float2 f; asm("mov.b64 {%0,%1},%2;" : "=f"(f.x), "=f"(f.y) : "l"(a)); return f;
}
__device__ __forceinline__ void cpa16(uint32_t d, const float* s) {
    asm volatile("cp.async.cg.shared.global [%0], [%1], 16;" :: "r"(d), "l"(s));
}
__device__ __forceinline__ void cpcommit() { asm volatile("cp.async.commit_group;"); }
__device__ __forceinline__ void cpwait2() { asm volatile("cp.async.wait_group 2;"); }
__device__ __forceinline__ float4 lds128f(uint32_t a) {
    float4 v;
    asm volatile("ld.shared.v4.f32 {%0,%1,%2,%3},[%4];"
                 : "=f"(v.x), "=f"(v.y), "=f"(v.z), "=f"(v.w) : "r"(a));
    return v;
}
__device__ __forceinline__ void lds2u64(uint32_t a, ull& p, ull& q) {
    asm volatile("ld.shared.v2.b64 {%0,%1},[%2];" : "=l"(p), "=l"(q) : "r"(a));
}
__device__ __forceinline__ float lds32(uint32_t a) {
    float v; asm volatile("ld.shared.f32 %0,[%1];" : "=f"(v) : "r"(a)); return v;
}

// ---------------- fused prep: weight transposes (gate-interleaved) + init ----------------
__global__ void __launch_bounds__(256) k_prep(const float* __restrict__ wih0,
                                              const float* __restrict__ whh0,
                                              const float* __restrict__ wih1,
                                              const float* __restrict__ whh1,
                                              const float* __restrict__ wout,
                                              const float* __restrict__ h0,
                                              const float* __restrict__ c0) {
    __shared__ float tl[32][33];
    int blk = blockIdx.x;
    int t = threadIdx.x;
    if (blk < 14336) {
        const float* in; float* out; int Km, koff, mb, nk;
        if (blk < 2048)       { in = wih0; out = d_w0T; Km = 512;  koff = 0;    mb = blk;         nk = 16; }
        else if (blk < 6144)  { in = whh0; out = d_w0T; Km = 1024; koff = 512;  mb = blk - 2048;  nk = 32; }
        else if (blk < 10240) { in = wih1; out = d_w1T; Km = 1024; koff = 0;    mb = blk - 6144;  nk = 32; }
        else                  { in = whh1; out = d_w1T; Km = 1024; koff = 1024; mb = blk - 10240; nk = 32; }
        int kt = mb % nk, jt = mb / nk;
#pragma unroll
        for (int q = 0; q < 4; q++) {
            int id = t + 256 * q; int kk = id & 31; int rr = id >> 5;
            int g = rr >> 3, j = rr & 7;
            tl[kk][j * 4 + g] = in[(size_t)(g * 1024 + jt * 8 + j) * Km + kt * 32 + kk];
        }
        __syncthreads();
#pragma unroll
        for (int q = 0; q < 4; q++) {
            int id = t + 256 * q; int c = id & 31; int kk = id >> 5;
            out[(size_t)(koff + kt * 32 + kk) * 4096 + jt * 32 + c] = tl[kk][c];
        }
    } else if (blk < 46368) {
        int mb = blk - 14336; int kt = mb % 32, rt = mb / 32;   // rt < 1001
#pragma unroll
        for (int q = 0; q < 4; q++) {
            int id = t + 256 * q; int kk = id & 31; int rr = id >> 5;
            int r = rt * 32 + rr;
            tl[rr][kk] = (r < VV) ? wout[(size_t)r * 1024 + kt * 32 + kk] : 0.f;
        }
        __syncthreads();
#pragma unroll
        for (int q = 0; q < 4; q++) {
            int id = t + 256 * q; int rr = id & 31; int kk = id >> 5;
            int r = rt * 32 + rr;
            if (r < PC) d_woT[(size_t)(kt * 32 + kk) * PC + r] = tl[rr][kk];
        }
    } else {
        int i = (blk - 46368) * 256 + t;   // < 65536
        int l = i >> 15; int r = i & 32767; int bb = r >> 10; int j = r & 1023;
        d_h[0][l][j * 32 + bb] = h0[i];
        d_cst[(l * 1024 + j) * 32 + bb] = c0[i];
        if (blk == 46368 && t < 32) { d_tok[t] = 32000; d_run[t] = 1; d_len[t] = 0; }
    }
}

// ---------------- fused select (argmax) + embedding gather ----------------
__global__ void __launch_bounds__(512) k_selembed(const float* __restrict__ emb,
                                                  float* __restrict__ outp,
                                                  int has_len, int s) {
    __shared__ float sv[128];
    __shared__ int   si[128];
    int b = blockIdx.x;
    int t = threadIdx.x;

    if (s > 0) {
        if (t < 128) {
            float best = -3.402823466e38f; int bi = 0x7fffffff;
            if (t < PB) { best = d_pmax[t * BB + b]; bi = d_pidx[t * BB + b]; }
            sv[t] = best; si[t] = bi;
        }
        __syncthreads();
        if (t == 0) {
            float best = sv[0]; int bi = si[0];
            for (int p = 1; p < 128; p++) {
                float v = sv[p]; int id = si[p];
                if (v > best || (v == best && id < bi)) { best = v; bi = id; }
            }
            d_tok[b] = bi;
            int r2 = d_run[b] && (bi != 32000);
            d_run[b] = r2;
            if (r2) d_len[b] = s;
            if (has_len) outp[(size_t)NSTEP * BB * VV + b] = (float)d_len[b];
        }
        __syncthreads();
    }
    int tok = d_tok[b];
    d_x[t * BB + b] = emb[(size_t)tok * EE + t];   // t = 0..511 == EE
}

// ---------------- fused gate GEMM + LSTM update (full K per block) ----------------
// grid 128 blocks, 256 threads; dyn smem 64KB (w ring 32KB + x ring 32KB)
__global__ void __launch_bounds__(256) k_gatesU(int layer, int parity,
                                                const float* __restrict__ bih,
                                                const float* __restrict__ bhh) {
    extern __shared__ __align__(16) char gsm[];
    uint32_t sbase = (uint32_t)__cvta_generic_to_shared(gsm);
    uint32_t wsb = sbase;            // 4 slots x 8KB
    uint32_t xsb = sbase + 32768;    // 4 slots x 8KB
    int t = threadIdx.x;
    const float* wT = layer ? d_w1T : d_w0T;
    int K = layer ? 2048 : 1536;
    int NST = K >> 6;                 // 64-k stages
    int split = layer ? 1024 : 512;
    const float* xa = layer ? d_h[1 - parity][0] : d_x;
    const float* xb = layer ? d_h[parity][1] : d_h[parity][0];
    float* hout = d_h[1 - parity][layer];
    int cb = blockIdx.x * 32;

    auto prefetch = [&](int s) {
        int slot = s & 3;
#pragma unroll
        for (int q = 0; q < 2; q++) {
            int p = t + 256 * q;          // 0..511
            int row = p >> 3, seg = p & 7;
            cpa16(wsb + slot * 8192 + row * 128 + seg * 16,
                  wT + (size_t)(s * 64 + row) * 4096 + cb + seg * 4);
        }
#pragma unroll
        for (int q = 0; q < 2; q++) {
            int p = t + 256 * q;
            int row = p >> 3, seg = p & 7;
            int kr = s * 64 + row;
            const float* src = (kr < split) ? (xa + (size_t)kr * 32 + seg * 4)
                                            : (xb + (size_t)(kr - split) * 32 + seg * 4);
            cpa16(xsb + slot * 8192 + row * 128 + seg * 16, src);
        }
        cpcommit();
    };
    prefetch(0); prefetch(1); prefetch(2);

    int j = t >> 5, b = t & 31;
    ull accif = 0ull, accgo = 0ull;
    for (int s = 0; s < NST; s++) {
        cpwait2();
        __syncthreads();
        int slot = s & 3;
        uint32_t wa = wsb + slot * 8192 + j * 16;
        uint32_t xadr = xsb + slot * 8192 + b * 4;
#pragma unroll 8
        for (int kk = 0; kk < 64; kk++) {
            ull wif, wgo;
            lds2u64(wa + kk * 128, wif, wgo);
            float xv = lds32(xadr + kk * 128);
            ull xx = pack2(xv, xv);
            accif = fma2(wif, xx, accif);
            accgo = fma2(wgo, xx, accgo);
        }
        __syncthreads();
        if (s + 3 < NST) prefetch(s + 3); else cpcommit();
    }
    // epilogue: bias + LSTM nonlinearity + state update
    int jg = blockIdx.x * 8 + j;
    float2 gif = unpk(accif), ggo = unpk(accgo);
    float gi = gif.x + bih[jg]        + bhh[jg];
    float gf = gif.y + bih[1024 + jg] + bhh[1024 + jg];
    float gg = ggo.x + bih[2048 + jg] + bhh[2048 + jg];
    float go = ggo.y + bih[3072 + jg] + bhh[3072 + jg];
    int ci = (layer * HH + jg) * BB + b;
    float c = d_cst[ci];
    float ig = 1.f / (1.f + expf(-gi));
    float fg = 1.f / (1.f + expf(-gf));
    float gt = tanhf(gg);
    float og = 1.f / (1.f + expf(-go));
    float c2 = fg * c + ig * gt;
    d_cst[ci] = c2;
    hout[jg * 32 + b] = og * tanhf(c2);
}

// ---------------- output projection: cp.async pipelined, 2 k-halves ----------------
// grid 126, 512 threads; dyn smem 147456 (w 2x4x16KB, x 2x4x2KB)
__global__ void __launch_bounds__(512) k_proj(const float* __restrict__ bias,
                                              float* __restrict__ outp,
                                              int s_step, int parity) {
    extern __shared__ __align__(16) char psm[];
    uint32_t sbase = (uint32_t)__cvta_generic_to_shared(psm);
    int tid = threadIdx.x;
    int half = tid >> 8;
    int t = tid & 255;
    const float* h1 = d_h[1 - parity][1];
    int cb = blockIdx.x * 256;
    uint32_t wsb = sbase + half * 65536;
    uint32_t xsb = sbase + 131072 + half * 8192;
    const float* wbase = d_woT + (size_t)(half * 512) * PC + cb;
    const float* xbase = h1 + (size_t)(half * 512) * 32;
    int barid = half + 1;

    auto prefetch = [&](int s) {
        int slot = s & 3;
#pragma unroll
        for (int q = 0; q < 4; q++) {
            int p = t + 256 * q;          // 0..1023
            int row = p >> 6, seg = p & 63;
            cpa16(wsb + slot * 16384 + row * 1024 + seg * 16,
                  wbase + (size_t)(s * 16 + row) * PC + seg * 4);
        }
        if (t < 128) {
            int row = t >> 3, seg = t & 7;
            cpa16(xsb + slot * 2048 + row * 128 + seg * 16,
                  xbase + (size_t)(s * 16 + row) * 32 + seg * 4);
        }
        cpcommit();
    };
    prefetch(0); prefetch(1); prefetch(2);

    int w = t >> 5, lane = t & 31, cl = lane & 7, bg = lane >> 3;
    int col = cb + w * 32 + cl * 4;

    ull acc[4][4];
#pragma unroll
    for (int i = 0; i < 4; i++)
#pragma unroll
        for (int j = 0; j < 4; j++) acc[i][j] = 0ull;

    for (int s = 0; s < 32; s++) {
        cpwait2();
        asm volatile("bar.sync %0, 256;" :: "r"(barid));
        uint32_t wa = wsb + (s & 3) * 16384 + w * 128 + cl * 16;
        uint32_t xadr = xsb + (s & 3) * 2048 + bg * 32;
#pragma unroll
        for (int kk = 0; kk < 16; kk++) {
            float4 w4 = lds128f(wa + kk * 1024);
            ull x0, x1, x2, x3;
            lds2u64(xadr + kk * 128, x0, x1);
            lds2u64(xadr + kk * 128 + 16, x2, x3);
            ull wv0 = pack2(w4.x, w4.x), wv1 = pack2(w4.y, w4.y);
            ull wv2 = pack2(w4.z, w4.z), wv3 = pack2(w4.w, w4.w);
            acc[0][0] = fma2(wv0, x0, acc[0][0]); acc[0][1] = fma2(wv0, x1, acc[0][1]);
            acc[0][2] = fma2(wv0, x2, acc[0][2]); acc[0][3] = fma2(wv0, x3, acc[0][3]);
            acc[1][0] = fma2(wv1, x0, acc[1][0]); acc[1][1] = fma2(wv1, x1, acc[1][1]);
            acc[1][2] = fma2(wv1, x2, acc[1][2]); acc[1][3] = fma2(wv1, x3, acc[1][3]);
            acc[2][0] = fma2(wv2, x0, acc[2][0]); acc[2][1] = fma2(wv2, x1, acc[2][1]);
            acc[2][2] = fma2(wv2, x2, acc[2][2]); acc[2][3] = fma2(wv2, x3, acc[2][3]);
            acc[3][0] = fma2(wv3, x0, acc[3][0]); acc[3][1] = fma2(wv3, x1, acc[3][1]);
            acc[3][2] = fma2(wv3, x2, acc[3][2]); acc[3][3] = fma2(wv3, x3, acc[3][3]);
        }
        asm volatile("bar.sync %0, 256;" :: "r"(barid));
        if (s + 3 < 32) prefetch(s + 3); else cpcommit();
    }
    __syncthreads();

    float f[32];
#pragma unroll
    for (int i = 0; i < 4; i++)
#pragma unroll
        for (int j = 0; j < 4; j++) {
            float2 u = unpk(acc[i][j]);
            f[i * 8 + 2 * j] = u.x;
            f[i * 8 + 2 * j + 1] = u.y;
        }

    float* ex = (float*)psm;                    // 32KB exchange (reuse stage smem)
    float* rv = (float*)(psm + 32768);          // [32][64]
    int*   ri = (int*)(psm + 40960);            // [32][64]

    if (half == 1) {
        float* ps = ex + (size_t)t * 32;
#pragma unroll
        for (int i = 0; i < 32; i++) ps[(i + t) & 31] = f[i];
    }
    __syncthreads();
    if (half == 0) {
        const float* ps = ex + (size_t)t * 32;
#pragma unroll
        for (int i = 0; i < 32; i++) f[i] += ps[(i + t) & 31];

        float bv[8]; int bx[8];
#pragma unroll
        for (int j = 0; j < 8; j++) { bv[j] = -3.402823466e38f; bx[j] = VV; }
#pragma unroll
        for (int i = 0; i < 4; i++) {
            int c = col + i;
            if (c < VV) {
                float bb = bias[c];
#pragma unroll
                for (int j = 0; j < 4; j++) {
                    float ux = f[i * 8 + 2 * j] + bb;
                    float uy = f[i * 8 + 2 * j + 1] + bb;
                    size_t o0 = (size_t)s_step * BB * VV + (size_t)(bg * 8 + 2 * j) * VV + c;
                    outp[o0] = ux;
                    outp[o0 + VV] = uy;
                    if (ux > bv[2 * j]     || (ux == bv[2 * j]     && c < bx[2 * j]))     { bv[2 * j] = ux;     bx[2 * j] = c; }
                    if (uy > bv[2 * j + 1] || (uy == bv[2 * j + 1] && c < bx[2 * j + 1])) { bv[2 * j + 1] = uy; bx[2 * j + 1] = c; }
                }
            }
        }
        int slot = w * 8 + cl;
#pragma unroll
        for (int j = 0; j < 8; j++) { rv[(bg * 8 + j) * 64 + slot] = bv[j]; ri[(bg * 8 + j) * 64 + slot] = bx[j]; }
    }
    __syncthreads();

    if (tid < BB) {
        float best = -3.402823466e38f; int bi = VV;
        for (int p = 0; p < 64; p++) {
            float v = rv[tid * 64 + p]; int id = ri[tid * 64 + p];
            if (v > best || (v == best && id < bi)) { best = v; bi = id; }
        }
        d_pmax[blockIdx.x * BB + tid] = best;
        d_pidx[blockIdx.x * BB + tid] = bi;
    }
}

// ---------------- launch ----------------
extern "C" void kernel_launch(void* const* d_in, const int* in_sizes, int n_in,
                              void* d_out, int out_size) {
    const float* h0   = (const float*)d_in[2];
    const float* c0   = (const float*)d_in[3];
    const float* emb  = (const float*)d_in[4];
    const float* wih0 = (const float*)d_in[5];
    const float* whh0 = (const float*)d_in[6];
    const float* bih0 = (const float*)d_in[7];
    const float* bhh0 = (const float*)d_in[8];
    const float* wih1 = (const float*)d_in[9];
    const float* whh1 = (const float*)d_in[10];
    const float* bih1 = (const float*)d_in[11];
    const float* bhh1 = (const float*)d_in[12];
    const float* wout = (const float*)d_in[13];
    const float* bout = (const float*)d_in[14];
    float* outp = (float*)d_out;
    int has_len = out_size > NSTEP * BB * VV;

    static int attr_done = 0;
    if (!attr_done) {
        cudaFuncSetAttribute(k_gatesU, cudaFuncAttributeMaxDynamicSharedMemorySize, 65536);
        cudaFuncSetAttribute(k_proj, cudaFuncAttributeMaxDynamicSharedMemorySize, 147456);
        attr_done = 1;
    }

    k_prep<<<46624, 256>>>(wih0, whh0, wih1, whh1, wout, h0, c0);

    for (int s = 0; s < NSTEP; s++) {
        int p = s & 1;
        k_selembed<<<BB, 512>>>(emb, outp, has_len, s);
        k_gatesU<<<128, 256, 65536>>>(0, p, bih0, bhh0);
        k_gatesU<<<128, 256, 65536>>>(1, p, bih1, bhh1);
        k_proj<<<PB, 512, 147456>>>(bout, outp, s, p);
    }
    k_selembed<<<BB, 512>>>(emb, outp, has_len, NSTEP);
}